// round 10
// baseline (speedup 1.0000x reference)
#include <cuda_runtime.h>

#define NN 8192
#define D 64
#define ALPHA 0.2f
#define CS 32          // scan chunk size (one warp-scan, no carry chain)
#define NC 256         // number of chunks (NN/CS)
#define HTS 33         // half-tile stride: 33 % 32 == 1 -> conflict-free columns

// ---------------- device scratch (no allocation allowed) ----------------
__device__ float g_h[NN * D];
__device__ float g_f1[NN];
__device__ float g_f2[NN];
__device__ unsigned g_key[NN];
__device__ unsigned g_rank[NN];        // low 20 bits: rank accum; bits 20+: arrival count
__device__ int   g_perm[NN];
__device__ float g_f2s[NN];
__device__ float g_wlo[NN];            // exp(alpha * f2), sorted order
__device__ float g_whi[NN];            // exp(f2), sorted order
__device__ float g_LoP[(NN + 1) * D];  // chunk-local fwd prefix of wlo*h
__device__ float g_HiS[(NN + 1) * D];  // chunk-local bwd suffix of whi*h
__device__ float g_zLo[NN + 1];
__device__ float g_zHi[NN + 1];
__device__ float g_tLo[D * NC];        // [d][c] chunk totals (kS2 reads unit-stride)
__device__ float g_tHi[D * NC];        // [d][c]
__device__ float g_ofLo[NC * D];       // [c][d] exclusive offsets (kOut reads coalesced)
__device__ float g_ofHi[NC * D];       // [c][d]
__device__ float g_ofzLo[NC];
__device__ float g_ofzHi[NC];

// ---------------- k1: h = x@Wt (16 rows/block), f1/f2, keys, zero ranks ----------------
__global__ void k1(const float* __restrict__ x, const float* __restrict__ Wt,
                   const float* __restrict__ a1, const float* __restrict__ b1,
                   const float* __restrict__ a2, const float* __restrict__ b2) {
    __shared__ float sW[D * D];
    __shared__ float sx[16][D];
    __shared__ float sh[16][D];
    int tid = threadIdx.x;        // 256
    int row0 = blockIdx.x * 16;
    for (int i = tid; i < D * D; i += 256) sW[i] = Wt[i];
    for (int i = tid; i < 16 * D; i += 256) sx[i >> 6][i & 63] = x[row0 * D + i];
    __syncthreads();
    int o = tid & 63, rg = tid >> 6;
    float a0 = 0.f, a1c = 0.f, a2c = 0.f, a3 = 0.f;
#pragma unroll
    for (int i = 0; i < D; i++) {
        float w = sW[i * D + o];
        a0  += sx[rg * 4 + 0][i] * w;
        a1c += sx[rg * 4 + 1][i] * w;
        a2c += sx[rg * 4 + 2][i] * w;
        a3  += sx[rg * 4 + 3][i] * w;
    }
    g_h[(row0 + rg * 4 + 0) * D + o] = a0;
    g_h[(row0 + rg * 4 + 1) * D + o] = a1c;
    g_h[(row0 + rg * 4 + 2) * D + o] = a2c;
    g_h[(row0 + rg * 4 + 3) * D + o] = a3;
    sh[rg * 4 + 0][o] = a0;
    sh[rg * 4 + 1][o] = a1c;
    sh[rg * 4 + 2][o] = a2c;
    sh[rg * 4 + 3][o] = a3;
    __syncthreads();
    int w = tid >> 5, lane = tid & 31;
#pragma unroll
    for (int q = 0; q < 2; q++) {
        int r = w * 2 + q;
        float h0 = sh[r][lane], h1 = sh[r][lane + 32];
        float s1 = h0 * a1[lane] + h1 * a1[lane + 32];
        float s2 = h0 * a2[lane] + h1 * a2[lane + 32];
#pragma unroll
        for (int off = 16; off; off >>= 1) {
            s1 += __shfl_down_sync(0xFFFFFFFFu, s1, off);
            s2 += __shfl_down_sync(0xFFFFFFFFu, s2, off);
        }
        if (lane == 0) {
            int row = row0 + r;
            float f1v = s1 + b1[0], f2v = s2 + b2[0];
            g_f1[row] = f1v;
            g_f2[row] = f2v;
            unsigned u = __float_as_uint(f2v);
            g_key[row] = (u >> 31) ? ~u : (u | 0x80000000u);  // order-preserving
            g_rank[row] = 0u;
        }
    }
}

// ---------------- kRank: counting rank + FUSED scatter (arrival counting) ----------------
// 1024 blocks = eb(64, element-chunk of 128) x cb(16, key-chunk of 512).
__global__ void kRank() {
    __shared__ unsigned sk[512];
    int tid = threadIdx.x;  // 128
    int eb = blockIdx.x >> 4, cb = blockIdx.x & 15;
    int i = eb * 128 + tid;
    unsigned ki = g_key[i];
#pragma unroll
    for (int m = 0; m < 4; m++) sk[tid + m * 128] = g_key[cb * 512 + tid + m * 128];
    __syncthreads();
    unsigned cnt = 0;
    int diag = eb >> 2;    // cb containing this eb's i-range
    if (cb == diag) {
        int j0 = cb * 512;
        for (int j = 0; j < 512; j++) {
            unsigned kj = sk[j];
            cnt += (kj < ki) || (kj == ki && (j0 + j) < i);
        }
    } else if (cb < diag) {   // all j < i: ties count
#pragma unroll 8
        for (int j = 0; j < 512; j++) cnt += (sk[j] <= ki);
    } else {                  // all j > i: ties don't count
#pragma unroll 8
        for (int j = 0; j < 512; j++) cnt += (sk[j] < ki);
    }
    unsigned old = atomicAdd(&g_rank[i], cnt + (1u << 20));
    if ((old >> 20) == 15u) {                 // final arrival performs scatter
        int r = (int)((old & 0xFFFFFu) + cnt);
        float f = g_f2[i];
        g_perm[r] = i;
        g_f2s[r] = f;
        g_wlo[r] = expf(ALPHA * f);
        g_whi[r] = expf(f);
    }
}

// ---------------- kScan: 512 blocks (chunk x d-half), BOTH tables per block ----------------
__global__ void kScan() {
    __shared__ float sLo[CS * HTS];       // 4224 B
    __shared__ float sHi[CS * HTS];       // 4224 B
    __shared__ int   sperm[CS];
    __shared__ float swlo[CS], swhi[CS];
    int tid = threadIdx.x;                // 256 (8 warps)
    int c = blockIdx.x >> 1, half = blockIdx.x & 1;
    int j0 = c * CS;
    int d0 = half * 32;
    if (tid < CS) {
        sperm[tid] = g_perm[j0 + tid];
        swlo[tid] = g_wlo[j0 + tid];
        swhi[tid] = g_whi[j0 + tid];
    }
    __syncthreads();
    int w = tid >> 5, lane = tid & 31;
#pragma unroll
    for (int it = 0; it < 4; it++) {
        int j = it * 8 + w;
        float hv = g_h[sperm[j] * D + d0 + lane];
        sLo[j * HTS + lane] = swlo[j] * hv;
        sHi[j * HTS + lane] = swhi[j] * hv;
    }
    if (half == 0 && tid < CS) {
        sLo[tid * HTS + 32] = swlo[tid];
        sHi[tid * HTS + 32] = swhi[tid];
    }
    __syncthreads();
    const unsigned F = 0xFFFFFFFFu;
    int ncols = (half == 0) ? 33 : 32;   // col 32 of half 0 = z column
    if (w < 4) {       // Lo forward scans
        for (int dd = w; dd < ncols; dd += 4) {
            float v = sLo[lane * HTS + dd];
#pragma unroll
            for (int o = 1; o < 32; o <<= 1) { float t = __shfl_up_sync(F, v, o); if (lane >= o) v += t; }
            sLo[lane * HTS + dd] = v;
            if (lane == 31) {
                if (dd < 32) g_tLo[(d0 + dd) * NC + c] = v; else g_ofzLo[c] = v;
            }
        }
    } else {           // Hi backward scans
        for (int dd = w - 4; dd < ncols; dd += 4) {
            float v = sHi[lane * HTS + dd];
#pragma unroll
            for (int o = 1; o < 32; o <<= 1) { float t = __shfl_down_sync(F, v, o); if (lane + o < 32) v += t; }
            sHi[lane * HTS + dd] = v;
            if (lane == 0) {
                if (dd < 32) g_tHi[(d0 + dd) * NC + c] = v; else g_ofzHi[c] = v;
            }
        }
    }
    __syncthreads();
#pragma unroll
    for (int it = 0; it < 4; it++) {
        int j = it * 8 + w;
        g_LoP[(j0 + j + 1) * D + d0 + lane] = sLo[j * HTS + lane];
        g_HiS[(j0 + j) * D + d0 + lane]     = sHi[j * HTS + lane];
    }
    if (half == 0 && tid < CS) {
        g_zLo[j0 + tid + 1] = sLo[tid * HTS + 32];
        g_zHi[j0 + tid]     = sHi[tid * HTS + 32];
    }
    if (c == 0) {
        if (tid < 32) g_LoP[d0 + tid] = 0.f;
        if (half == 0 && tid == 32) g_zLo[0] = 0.f;
    }
    if (c == NC - 1) {
        if (tid < 32) g_HiS[NN * D + d0 + tid] = 0.f;
        if (half == 0 && tid == 32) g_zHi[NN] = 0.f;
    }
}

// ---------------- kS2: unit-stride reads from [d][c], strided stores to [c][d] ----------------
__global__ void kS2() {
    int t = blockIdx.x * 4 + (threadIdx.x >> 5);
    int lane = threadIdx.x & 31;
    if (t >= 130) return;
    const unsigned F = 0xFFFFFFFFu;
    const float* in;
    float* out;
    int ostride;
    bool fwd;
    if (t < 64)        { in = g_tLo + t * NC;        out = g_ofLo + t;        ostride = D; fwd = true;  }
    else if (t < 128)  { in = g_tHi + (t - 64) * NC; out = g_ofHi + (t - 64); ostride = D; fwd = false; }
    else if (t == 128) { in = g_ofzLo;               out = g_ofzLo;           ostride = 1; fwd = true;  }
    else               { in = g_ofzHi;               out = g_ofzHi;           ostride = 1; fwd = false; }
    float carry = 0.f;
    if (fwd) {
#pragma unroll
        for (int m = 0; m < 8; m++) {
            float v = in[m * 32 + lane];
            float x = v;
#pragma unroll
            for (int o = 1; o < 32; o <<= 1) { float s = __shfl_up_sync(F, x, o); if (lane >= o) x += s; }
            float incl = x + carry;
            out[(m * 32 + lane) * ostride] = incl - v;   // exclusive prefix
            carry = __shfl_sync(F, incl, 31);
        }
    } else {
#pragma unroll
        for (int m = 7; m >= 0; m--) {
            float v = in[m * 32 + lane];
            float x = v;
#pragma unroll
            for (int o = 1; o < 32; o <<= 1) { float s = __shfl_down_sync(F, x, o); if (lane + o < 32) x += s; }
            float incl = x + carry;
            out[(m * 32 + lane) * ostride] = incl - v;   // exclusive suffix
            carry = __shfl_sync(F, incl, 0);
        }
    }
}

// ---------------- kOut: per-row combine + ELU (coalesced offsets) ----------------
__global__ void kOut(float* __restrict__ out) {
    __shared__ float sf[256];             // f2s samples at stride 32
    int tid = threadIdx.x;                // 256
    sf[tid] = g_f2s[tid * 32];
    __syncthreads();
    int w = tid >> 5, lane = tid & 31;
    int i = blockIdx.x * 8 + w;
    float f1 = g_f1[i];
    float thr = -f1;
    const unsigned F = 0xFFFFFFFFu;
    int lo = 0, hi = 256;
#pragma unroll
    for (int it = 0; it < 8; it++) { int m = (lo + hi) >> 1; lo = (sf[m] <= thr) ? m + 1 : lo; hi = (sf[m] <= thr) ? hi : m; }
    int k;
    if (lo == 0) {
        __ballot_sync(F, false);
        k = 0;
    } else {
        int win = lo - 1;                 // f2s[win*32] <= thr; k in [win*32+1, win*32+32]
        int idx = win * 32 + 1 + lane;
        unsigned m = __ballot_sync(F, (idx < NN) ? (g_f2s[idx] <= thr) : false);
        k = win * 32 + 1 + __popc(m);
    }
    int ckLo = (k == 0) ? 0 : ((k - 1) >> 5);
    int ckHi = k >> 5;
    bool hasHi = (k < NN);
    float e1 = expf(f1), ea = expf(ALPHA * f1);
    float zLoV = g_zLo[k] + g_ofzLo[ckLo];
    float zHiV = hasHi ? (g_zHi[k] + g_ofzHi[ckHi]) : 0.f;
    float inv = 1.0f / (e1 * zHiV + ea * zLoV);
#pragma unroll
    for (int p = 0; p < 2; p++) {
        int d = lane + 32 * p;
        float lov = g_LoP[k * D + d] + g_ofLo[ckLo * D + d];
        float hiv = hasHi ? (g_HiS[k * D + d] + g_ofHi[ckHi * D + d]) : 0.f;
        float r = (e1 * hiv + ea * lov) * inv;
        out[i * D + d] = (r > 0.f) ? r : (expf(r) - 1.f);
    }
}

extern "C" void kernel_launch(void* const* d_in, const int* in_sizes, int n_in,
                              void* d_out, int out_size) {
    const float* x  = (const float*)d_in[0];
    const float* Wt = (const float*)d_in[1];
    const float* a1 = (const float*)d_in[2];
    const float* b1 = (const float*)d_in[3];
    const float* a2 = (const float*)d_in[4];
    const float* b2 = (const float*)d_in[5];
    float* out = (float*)d_out;

    k1<<<NN / 16, 256>>>(x, Wt, a1, b1, a2, b2);
    kRank<<<1024, 128>>>();
    kScan<<<NC * 2, 256>>>();
    kS2<<<33, 128>>>();
    kOut<<<NN / 8, 256>>>(out);
}

// round 11
// speedup vs baseline: 1.0062x; 1.0062x over previous
#include <cuda_runtime.h>

#define NN 8192
#define D 64
#define ALPHA 0.2f
#define CS 32          // scan chunk size (one warp-scan, no carry chain)
#define NC 256         // number of chunks (NN/CS)
#define HTS 33         // half-tile stride: 33 % 32 == 1 -> conflict-free columns

// ---------------- device scratch (no allocation allowed) ----------------
__device__ float g_h[NN * D];
__device__ float g_f1[NN];
__device__ float g_f2[NN];
__device__ unsigned g_key[NN];
__device__ unsigned g_rank[NN];        // low 20 bits: rank accum; bits 20+: arrival count
__device__ int   g_perm[NN];
__device__ float g_f2s[NN];
__device__ float g_wlo[NN];            // exp(alpha * f2), sorted order
__device__ float g_whi[NN];            // exp(f2), sorted order
__device__ float g_LoP[(NN + 1) * D];  // chunk-local fwd prefix of wlo*h
__device__ float g_HiS[(NN + 1) * D];  // chunk-local bwd suffix of whi*h
__device__ float g_zLo[NN + 1];
__device__ float g_zHi[NN + 1];
__device__ float g_ofLo[D * NC];       // [d][c] totals -> exclusive offsets (in place)
__device__ float g_ofHi[D * NC];       // [d][c]
__device__ float g_ofzLo[NC];
__device__ float g_ofzHi[NC];

// ---------------- k1: h = x@Wt (16 rows/block), f1/f2, keys, zero ranks ----------------
__global__ void k1(const float* __restrict__ x, const float* __restrict__ Wt,
                   const float* __restrict__ a1, const float* __restrict__ b1,
                   const float* __restrict__ a2, const float* __restrict__ b2) {
    __shared__ float sW[D * D];
    __shared__ float sx[16][D];
    __shared__ float sh[16][D];
    int tid = threadIdx.x;        // 256
    int row0 = blockIdx.x * 16;
    for (int i = tid; i < D * D; i += 256) sW[i] = Wt[i];
    for (int i = tid; i < 16 * D; i += 256) sx[i >> 6][i & 63] = x[row0 * D + i];
    __syncthreads();
    int o = tid & 63, rg = tid >> 6;
    float a0 = 0.f, a1c = 0.f, a2c = 0.f, a3 = 0.f;
#pragma unroll
    for (int i = 0; i < D; i++) {
        float w = sW[i * D + o];
        a0  += sx[rg * 4 + 0][i] * w;
        a1c += sx[rg * 4 + 1][i] * w;
        a2c += sx[rg * 4 + 2][i] * w;
        a3  += sx[rg * 4 + 3][i] * w;
    }
    g_h[(row0 + rg * 4 + 0) * D + o] = a0;
    g_h[(row0 + rg * 4 + 1) * D + o] = a1c;
    g_h[(row0 + rg * 4 + 2) * D + o] = a2c;
    g_h[(row0 + rg * 4 + 3) * D + o] = a3;
    sh[rg * 4 + 0][o] = a0;
    sh[rg * 4 + 1][o] = a1c;
    sh[rg * 4 + 2][o] = a2c;
    sh[rg * 4 + 3][o] = a3;
    __syncthreads();
    int w = tid >> 5, lane = tid & 31;
#pragma unroll
    for (int q = 0; q < 2; q++) {
        int r = w * 2 + q;
        float h0 = sh[r][lane], h1 = sh[r][lane + 32];
        float s1 = h0 * a1[lane] + h1 * a1[lane + 32];
        float s2 = h0 * a2[lane] + h1 * a2[lane + 32];
#pragma unroll
        for (int off = 16; off; off >>= 1) {
            s1 += __shfl_down_sync(0xFFFFFFFFu, s1, off);
            s2 += __shfl_down_sync(0xFFFFFFFFu, s2, off);
        }
        if (lane == 0) {
            int row = row0 + r;
            float f1v = s1 + b1[0], f2v = s2 + b2[0];
            g_f1[row] = f1v;
            g_f2[row] = f2v;
            unsigned u = __float_as_uint(f2v);
            g_key[row] = (u >> 31) ? ~u : (u | 0x80000000u);  // order-preserving
            g_rank[row] = 0u;
        }
    }
}

// ---------------- kRank: counting rank + FUSED scatter (arrival counting) ----------------
// 1024 blocks = eb(64, element-chunk of 128) x cb(16, key-chunk of 512).
__global__ void kRank() {
    __shared__ unsigned sk[512];
    int tid = threadIdx.x;  // 128
    int eb = blockIdx.x >> 4, cb = blockIdx.x & 15;
    int i = eb * 128 + tid;
    unsigned ki = g_key[i];
#pragma unroll
    for (int m = 0; m < 4; m++) sk[tid + m * 128] = g_key[cb * 512 + tid + m * 128];
    __syncthreads();
    unsigned cnt = 0;
    int diag = eb >> 2;    // cb containing this eb's i-range
    if (cb == diag) {
        int j0 = cb * 512;
        for (int j = 0; j < 512; j++) {
            unsigned kj = sk[j];
            cnt += (kj < ki) || (kj == ki && (j0 + j) < i);
        }
    } else if (cb < diag) {   // all j < i: ties count
#pragma unroll 8
        for (int j = 0; j < 512; j++) cnt += (sk[j] <= ki);
    } else {                  // all j > i: ties don't count
#pragma unroll 8
        for (int j = 0; j < 512; j++) cnt += (sk[j] < ki);
    }
    unsigned old = atomicAdd(&g_rank[i], cnt + (1u << 20));
    if ((old >> 20) == 15u) {                 // final arrival performs scatter
        int r = (int)((old & 0xFFFFFu) + cnt);
        float f = g_f2[i];
        g_perm[r] = i;
        g_f2s[r] = f;
        g_wlo[r] = expf(ALPHA * f);
        g_whi[r] = expf(f);
    }
}

// ---------------- kScan: 512 blocks (chunk x d-half), BOTH tables per block ----------------
__global__ void kScan() {
    __shared__ float sLo[CS * HTS];       // 4224 B
    __shared__ float sHi[CS * HTS];       // 4224 B
    __shared__ int   sperm[CS];
    __shared__ float swlo[CS], swhi[CS];
    int tid = threadIdx.x;                // 256 (8 warps)
    int c = blockIdx.x >> 1, half = blockIdx.x & 1;
    int j0 = c * CS;
    int d0 = half * 32;
    if (tid < CS) {
        sperm[tid] = g_perm[j0 + tid];
        swlo[tid] = g_wlo[j0 + tid];
        swhi[tid] = g_whi[j0 + tid];
    }
    __syncthreads();
    int w = tid >> 5, lane = tid & 31;
#pragma unroll
    for (int it = 0; it < 4; it++) {
        int j = it * 8 + w;
        float hv = g_h[sperm[j] * D + d0 + lane];
        sLo[j * HTS + lane] = swlo[j] * hv;
        sHi[j * HTS + lane] = swhi[j] * hv;
    }
    if (half == 0 && tid < CS) {
        sLo[tid * HTS + 32] = swlo[tid];
        sHi[tid * HTS + 32] = swhi[tid];
    }
    __syncthreads();
    const unsigned F = 0xFFFFFFFFu;
    int ncols = (half == 0) ? 33 : 32;   // col 32 of half 0 = z column
    if (w < 4) {       // Lo forward scans
        for (int dd = w; dd < ncols; dd += 4) {
            float v = sLo[lane * HTS + dd];
#pragma unroll
            for (int o = 1; o < 32; o <<= 1) { float t = __shfl_up_sync(F, v, o); if (lane >= o) v += t; }
            sLo[lane * HTS + dd] = v;
            if (lane == 31) {
                if (dd < 32) g_ofLo[(d0 + dd) * NC + c] = v; else g_ofzLo[c] = v;
            }
        }
    } else {           // Hi backward scans
        for (int dd = w - 4; dd < ncols; dd += 4) {
            float v = sHi[lane * HTS + dd];
#pragma unroll
            for (int o = 1; o < 32; o <<= 1) { float t = __shfl_down_sync(F, v, o); if (lane + o < 32) v += t; }
            sHi[lane * HTS + dd] = v;
            if (lane == 0) {
                if (dd < 32) g_ofHi[(d0 + dd) * NC + c] = v; else g_ofzHi[c] = v;
            }
        }
    }
    __syncthreads();
#pragma unroll
    for (int it = 0; it < 4; it++) {
        int j = it * 8 + w;
        g_LoP[(j0 + j + 1) * D + d0 + lane] = sLo[j * HTS + lane];
        g_HiS[(j0 + j) * D + d0 + lane]     = sHi[j * HTS + lane];
    }
    if (half == 0 && tid < CS) {
        g_zLo[j0 + tid + 1] = sLo[tid * HTS + 32];
        g_zHi[j0 + tid]     = sHi[tid * HTS + 32];
    }
    if (c == 0) {
        if (tid < 32) g_LoP[d0 + tid] = 0.f;
        if (half == 0 && tid == 32) g_zLo[0] = 0.f;
    }
    if (c == NC - 1) {
        if (tid < 32) g_HiS[NN * D + d0 + tid] = 0.f;
        if (half == 0 && tid == 32) g_zHi[NN] = 0.f;
    }
}

// ---------------- kS2: in-place unit-stride scan of [d][c] chunk totals ----------------
__global__ void kS2() {
    int t = blockIdx.x * 4 + (threadIdx.x >> 5);
    int lane = threadIdx.x & 31;
    if (t >= 130) return;
    const unsigned F = 0xFFFFFFFFu;
    float* base;
    bool fwd;
    if (t < 64)        { base = g_ofLo + t * NC;        fwd = true;  }
    else if (t < 128)  { base = g_ofHi + (t - 64) * NC; fwd = false; }
    else if (t == 128) { base = g_ofzLo;                fwd = true;  }
    else               { base = g_ofzHi;                fwd = false; }
    float carry = 0.f;
    if (fwd) {
#pragma unroll
        for (int m = 0; m < 8; m++) {
            float v = base[m * 32 + lane];
            float x = v;
#pragma unroll
            for (int o = 1; o < 32; o <<= 1) { float s = __shfl_up_sync(F, x, o); if (lane >= o) x += s; }
            float incl = x + carry;
            base[m * 32 + lane] = incl - v;        // exclusive prefix
            carry = __shfl_sync(F, incl, 31);
        }
    } else {
#pragma unroll
        for (int m = 7; m >= 0; m--) {
            float v = base[m * 32 + lane];
            float x = v;
#pragma unroll
            for (int o = 1; o < 32; o <<= 1) { float s = __shfl_down_sync(F, x, o); if (lane + o < 32) x += s; }
            float incl = x + carry;
            base[m * 32 + lane] = incl - v;        // exclusive suffix
            carry = __shfl_sync(F, incl, 0);
        }
    }
}

// ---------------- kOut: per-row combine + ELU ----------------
__global__ void kOut(float* __restrict__ out) {
    __shared__ float sf[256];             // f2s samples at stride 32
    int tid = threadIdx.x;                // 256
    sf[tid] = g_f2s[tid * 32];
    __syncthreads();
    int w = tid >> 5, lane = tid & 31;
    int i = blockIdx.x * 8 + w;
    float f1 = g_f1[i];
    float thr = -f1;
    const unsigned F = 0xFFFFFFFFu;
    int lo = 0, hi = 256;
#pragma unroll
    for (int it = 0; it < 8; it++) { int m = (lo + hi) >> 1; lo = (sf[m] <= thr) ? m + 1 : lo; hi = (sf[m] <= thr) ? hi : m; }
    int k;
    if (lo == 0) {
        __ballot_sync(F, false);
        k = 0;
    } else {
        int win = lo - 1;                 // f2s[win*32] <= thr; k in [win*32+1, win*32+32]
        int idx = win * 32 + 1 + lane;
        unsigned m = __ballot_sync(F, (idx < NN) ? (g_f2s[idx] <= thr) : false);
        k = win * 32 + 1 + __popc(m);
    }
    int ckLo = (k == 0) ? 0 : ((k - 1) >> 5);
    int ckHi = k >> 5;
    bool hasHi = (k < NN);
    float e1 = expf(f1), ea = expf(ALPHA * f1);
    float zLoV = g_zLo[k] + g_ofzLo[ckLo];
    float zHiV = hasHi ? (g_zHi[k] + g_ofzHi[ckHi]) : 0.f;
    float inv = 1.0f / (e1 * zHiV + ea * zLoV);
#pragma unroll
    for (int p = 0; p < 2; p++) {
        int d = lane + 32 * p;
        float lov = g_LoP[k * D + d] + g_ofLo[d * NC + ckLo];
        float hiv = hasHi ? (g_HiS[k * D + d] + g_ofHi[d * NC + ckHi]) : 0.f;
        float r = (e1 * hiv + ea * lov) * inv;
        out[i * D + d] = (r > 0.f) ? r : (expf(r) - 1.f);
    }
}

extern "C" void kernel_launch(void* const* d_in, const int* in_sizes, int n_in,
                              void* d_out, int out_size) {
    const float* x  = (const float*)d_in[0];
    const float* Wt = (const float*)d_in[1];
    const float* a1 = (const float*)d_in[2];
    const float* b1 = (const float*)d_in[3];
    const float* a2 = (const float*)d_in[4];
    const float* b2 = (const float*)d_in[5];
    float* out = (float*)d_out;

    k1<<<NN / 16, 256>>>(x, Wt, a1, b1, a2, b2);
    kRank<<<1024, 128>>>();
    kScan<<<NC * 2, 256>>>();
    kS2<<<33, 128>>>();
    kOut<<<NN / 8, 256>>>(out);
}